// round 16
// baseline (speedup 1.0000x reference)
#include <cuda_runtime.h>
#include <math.h>
#include <stdint.h>

// Problem constants (fixed by the dataset)
#define Nn 100000
#define Ee 1600000
#define NE_TOT (Ee + Nn)          // edges + self loops
#define F1 64                     // heads*hid  (8*8)
#define F2 128                    // heads*out  (8*16)
#define IN_CH 512
#define NEG_SLOPE 0.2f

// ---------------- device scratch (static allocation: allowed) ----------------
__device__ int   g_is64;          // 1 if edge_index is int64, 0 if int32
__device__ int   g_count[Nn];
__device__ int   g_offsets[Nn + 1];
__device__ int   g_bsum[128];
__device__ int   g_cursor[Nn];
__device__ int   g_col[NE_TOT + 8];   // +8 pad (zero-init): prefetch-safe
__device__ __align__(16) float g_h1[(size_t)Nn * F1];     // gemm1 output
__device__ __align__(16) float g_h1act[(size_t)Nn * F1];  // layer1 aggregated + elu
__device__ __align__(16) float g_h2[(size_t)Nn * F2];     // gemm2 output

// ---------------- packed fp32x2 helpers (Blackwell FFMA2) -------------------
__device__ __forceinline__ unsigned long long pack2(float lo, float hi) {
    unsigned long long r;
    asm("mov.b64 %0, {%1, %2};" : "=l"(r) : "f"(lo), "f"(hi));
    return r;
}
__device__ __forceinline__ void ffma2(unsigned long long &d, unsigned long long a,
                                      unsigned long long b) {
    asm("fma.rn.f32x2 %0, %1, %2, %0;" : "+l"(d) : "l"(a), "l"(b));
}
__device__ __forceinline__ void unpack2(unsigned long long v, float &lo, float &hi) {
    asm("mov.b64 {%0, %1}, %2;" : "=f"(lo), "=f"(hi) : "l"(v));
}

// ---------------- cp.async helpers ------------------------------------------
__device__ __forceinline__ uint32_t smem_u32(const void* p) {
    return (uint32_t)__cvta_generic_to_shared(p);
}
__device__ __forceinline__ void cp_async16(uint32_t dst, const void* src, int src_bytes) {
    asm volatile("cp.async.ca.shared.global [%0], [%1], 16, %2;"
                 :: "r"(dst), "l"(src), "r"(src_bytes));
}
__device__ __forceinline__ void cp_commit() {
    asm volatile("cp.async.commit_group;");
}
__device__ __forceinline__ void cp_wait_all() {
    asm volatile("cp.async.wait_group 0;");
}

// ============================ dtype detection ===============================
__global__ void k_detect(const void* ei) {
    __shared__ int s_bad;
    if (threadIdx.x == 0) s_bad = 0;
    __syncthreads();
    long long v = ((const long long*)ei)[threadIdx.x];   // 64 threads
    if (v < 0 || v >= Nn) atomicAdd(&s_bad, 1);
    __syncthreads();
    if (threadIdx.x == 0) g_is64 = (s_bad == 0) ? 1 : 0;
}

__device__ __forceinline__ int load_idx(const void* ei, size_t pos, int is64) {
    return is64 ? (int)((const long long*)ei)[pos] : ((const int*)ei)[pos];
}

// ============================ CSR build =====================================
__global__ void k_init_count() {
    int i = blockIdx.x * blockDim.x + threadIdx.x;
    if (i < Nn) g_count[i] = 1;   // self loop
}

__global__ void k_count(const void* __restrict__ ei) {
    int e = blockIdx.x * blockDim.x + threadIdx.x;
    if (e < Ee) {
        int is64 = g_is64;
        int dst = load_idx(ei, (size_t)Ee + e, is64);
        if ((unsigned)dst < (unsigned)Nn)
            atomicAdd(&g_count[dst], 1);
    }
}

__global__ void k_scan1() {
    __shared__ int warpsum[8];
    int t = threadIdx.x;
    int lane = t & 31;
    int wid = t >> 5;
    int base = blockIdx.x * 1024 + t * 4;

    int c0 = (base + 0 < Nn) ? g_count[base + 0] : 0;
    int c1 = (base + 1 < Nn) ? g_count[base + 1] : 0;
    int c2 = (base + 2 < Nn) ? g_count[base + 2] : 0;
    int c3 = (base + 3 < Nn) ? g_count[base + 3] : 0;
    int tot = c0 + c1 + c2 + c3;

    int v = tot;
#pragma unroll
    for (int off = 1; off < 32; off <<= 1) {
        int n = __shfl_up_sync(0xffffffffu, v, off);
        if (lane >= off) v += n;
    }
    if (lane == 31) warpsum[wid] = v;
    __syncthreads();
    if (t == 0) {
        int run = 0;
#pragma unroll
        for (int i = 0; i < 8; i++) { int x = warpsum[i]; warpsum[i] = run; run += x; }
    }
    __syncthreads();

    int exc = warpsum[wid] + (v - tot);
    if (base + 0 < Nn) g_offsets[base + 0] = exc;
    exc += c0;
    if (base + 1 < Nn) g_offsets[base + 1] = exc;
    exc += c1;
    if (base + 2 < Nn) g_offsets[base + 2] = exc;
    exc += c2;
    if (base + 3 < Nn) g_offsets[base + 3] = exc;

    if (t == 255) g_bsum[blockIdx.x] = warpsum[7] + v;
}

__global__ void k_scan2() {
    int lane = threadIdx.x;   // <<<1,32>>>
    int run = 0;
#pragma unroll
    for (int c = 0; c < 4; c++) {
        int idx = c * 32 + lane;
        int x = (idx < 98) ? g_bsum[idx] : 0;
        int v = x;
#pragma unroll
        for (int off = 1; off < 32; off <<= 1) {
            int n = __shfl_up_sync(0xffffffffu, v, off);
            if (lane >= off) v += n;
        }
        if (idx < 98) g_bsum[idx] = run + (v - x);
        run += __shfl_sync(0xffffffffu, v, 31);
    }
}

__global__ void k_scan3() {
    int g = blockIdx.x * blockDim.x + threadIdx.x;
    if (g < Nn) {
        int o = g_offsets[g] + g_bsum[g >> 10];
        g_offsets[g] = o;
        g_cursor[g] = o;
    }
    if (g == 0) g_offsets[Nn] = NE_TOT;
}

__global__ void k_fill(const void* __restrict__ ei) {
    int t = blockIdx.x * blockDim.x + threadIdx.x;
    if (t >= NE_TOT) return;
    if (t < Ee) {
        int is64 = g_is64;
        int src = load_idx(ei, (size_t)t, is64);
        int dst = load_idx(ei, (size_t)Ee + t, is64);
        if ((unsigned)src < (unsigned)Nn && (unsigned)dst < (unsigned)Nn) {
            int pos = atomicAdd(&g_cursor[dst], 1);
            if ((unsigned)pos < (unsigned)NE_TOT) g_col[pos] = src;
        }
    } else {
        int i = t - Ee;
        int pos = atomicAdd(&g_cursor[i], 1);
        if ((unsigned)pos < (unsigned)NE_TOT) g_col[pos] = i;   // self loop
    }
}

// ============================ GEMM 1: x[N,512] @ W1[512,64] =================
// 256 threads, 128x64 tile, 4x8 thread tile, FFMA2, cp.async double buffer.
// Rows LUT-permuted so each warp's 4 row-tiles hit 4 distinct XOR groups ->
// conflict-free swizzled A loads (4 quads x 8-lane broadcast).
__global__ __launch_bounds__(256, 3) void k_gemm1(const float* __restrict__ x,
                                                  const float* __restrict__ W) {
    __shared__ float As[2][128][32];   // 2 x 16 KB, XOR-swizzled
    __shared__ float Bs[2][32][64];    // 2 x 8 KB   (48 KB total)

    int tid = threadIdx.x;
    int row0 = blockIdx.x * 128;
    int ry = tid >> 3;       // 0..31
    int cx = tid & 7;        // cols {4cx..+3} and {32+4cx..+3}

    // per-warp: ry&3 distinct 0..3, ry>>2 constant -> 4 distinct groups mod 8
    const int lut[8] = {0, 4, 32, 36, 64, 68, 96, 100};
    int row_base = (ry & 3) * 8 + lut[ry >> 2];    // 4-row tile start
    int gsw = (row_base >> 3) & 7;                 // XOR key for compute loads

    unsigned long long acc[4][4];   // [row][colpair]
#pragma unroll
    for (int r = 0; r < 4; r++)
#pragma unroll
        for (int c = 0; c < 4; c++) acc[r][c] = 0ull;

    auto load_tile = [&](int k0, int buf) {
#pragma unroll
        for (int it = 0; it < 4; it++) {           // A: 1024 float4 / 256 thr
            int s = it * 256 + tid;
            int r = s >> 3;                        // 0..127
            int kq = s & 7;
            int col4 = kq ^ ((r >> 3) & 7);
            uint32_t dst = smem_u32(&As[buf][r][col4 * 4]);
            int grow = row0 + r;
            const float* src = x + (size_t)(grow < Nn ? grow : 0) * IN_CH + k0 + kq * 4;
            cp_async16(dst, src, (grow < Nn) ? 16 : 0);
        }
#pragma unroll
        for (int it = 0; it < 2; it++) {           // B: 512 float4 / 256 thr
            int s = it * 256 + tid;
            int kk = s >> 4;                       // 0..31
            int cq = s & 15;
            uint32_t dst = smem_u32(&Bs[buf][kk][cq * 4]);
            cp_async16(dst, W + (size_t)(k0 + kk) * F1 + cq * 4, 16);
        }
        cp_commit();
    };

    load_tile(0, 0);

    for (int itile = 0; itile < 16; itile++) {
        int buf = itile & 1;
        cp_wait_all();
        __syncthreads();
        if (itile + 1 < 16) load_tile((itile + 1) * 32, buf ^ 1);

#pragma unroll
        for (int k4 = 0; k4 < 8; k4++) {
            int ck = k4 ^ gsw;
            float4 a4[4];
#pragma unroll
            for (int j = 0; j < 4; j++)
                a4[j] = *reinterpret_cast<const float4*>(&As[buf][row_base + j][ck * 4]);
#pragma unroll
            for (int t = 0; t < 4; t++) {
                int k = k4 * 4 + t;
                ulonglong2 bv0 = *reinterpret_cast<const ulonglong2*>(&Bs[buf][k][cx * 4]);
                ulonglong2 bv1 = *reinterpret_cast<const ulonglong2*>(&Bs[buf][k][32 + cx * 4]);
#pragma unroll
                for (int j = 0; j < 4; j++) {
                    float av = (t == 0) ? a4[j].x : (t == 1) ? a4[j].y
                             : (t == 2) ? a4[j].z : a4[j].w;
                    unsigned long long ap = pack2(av, av);
                    ffma2(acc[j][0], ap, bv0.x);
                    ffma2(acc[j][1], ap, bv0.y);
                    ffma2(acc[j][2], ap, bv1.x);
                    ffma2(acc[j][3], ap, bv1.y);
                }
            }
        }
        __syncthreads();
    }

#pragma unroll
    for (int j = 0; j < 4; j++) {
        int grow = row0 + row_base + j;
        if (grow < Nn) {
            float o[8];
#pragma unroll
            for (int c = 0; c < 4; c++) unpack2(acc[j][c], o[c * 2], o[c * 2 + 1]);
            float* dst = &g_h1[(size_t)grow * F1];
            *reinterpret_cast<float4*>(dst + cx * 4)      = make_float4(o[0], o[1], o[2], o[3]);
            *reinterpret_cast<float4*>(dst + 32 + cx * 4) = make_float4(o[4], o[5], o[6], o[7]);
        }
    }
}

// ============================ GEMM 2: h1act[N,64] @ W2[64,128] ==============
__global__ void k_gemm2(const float* __restrict__ W) {
    __shared__ float As[64][68];    // [k][row], pad 68 -> 16B-aligned rows
    __shared__ float Bs[32][132];

    int tid = threadIdx.x;
    int row0 = blockIdx.x * 64;
    int ry = tid >> 4;
    int cx = tid & 15;

#pragma unroll
    for (int it = 0; it < 4; it++) {
        int s = it * 256 + tid;
        int r = s >> 4;
        int kq = s & 15;
        int grow = row0 + r;
        float4 v = make_float4(0.f, 0.f, 0.f, 0.f);
        if (grow < Nn)
            v = *reinterpret_cast<const float4*>(&g_h1act[(size_t)grow * F1 + kq * 4]);
        As[kq * 4 + 0][r] = v.x;
        As[kq * 4 + 1][r] = v.y;
        As[kq * 4 + 2][r] = v.z;
        As[kq * 4 + 3][r] = v.w;
    }

    unsigned long long acc[4][4];
#pragma unroll
    for (int r = 0; r < 4; r++)
#pragma unroll
        for (int c = 0; c < 4; c++) acc[r][c] = 0ull;

    for (int kc = 0; kc < 64; kc += 32) {
#pragma unroll
        for (int it = 0; it < 4; it++) {
            int s = it * 256 + tid;
            int kk = s >> 5;
            int cq = s & 31;
            float4 v = *reinterpret_cast<const float4*>(W + (size_t)(kc + kk) * F2 + cq * 4);
            *reinterpret_cast<float4*>(&Bs[kk][cq * 4]) = v;
        }
        __syncthreads();

#pragma unroll
        for (int k = 0; k < 32; k++) {
            float4 a = *reinterpret_cast<const float4*>(&As[kc + k][ry * 4]);
            ulonglong2 bv0 = *reinterpret_cast<const ulonglong2*>(&Bs[k][cx * 4]);
            ulonglong2 bv1 = *reinterpret_cast<const ulonglong2*>(&Bs[k][64 + cx * 4]);
            float av[4] = {a.x, a.y, a.z, a.w};
#pragma unroll
            for (int r = 0; r < 4; r++) {
                unsigned long long ap = pack2(av[r], av[r]);
                ffma2(acc[r][0], ap, bv0.x);
                ffma2(acc[r][1], ap, bv0.y);
                ffma2(acc[r][2], ap, bv1.x);
                ffma2(acc[r][3], ap, bv1.y);
            }
        }
        __syncthreads();
    }

#pragma unroll
    for (int r = 0; r < 4; r++) {
        int grow = row0 + ry * 4 + r;
        if (grow < Nn) {
            float o[8];
#pragma unroll
            for (int c = 0; c < 4; c++) unpack2(acc[r][c], o[c * 2], o[c * 2 + 1]);
            float* dst = &g_h2[(size_t)grow * F2];
            *reinterpret_cast<float4*>(dst + cx * 4) =
                make_float4(o[0], o[1], o[2], o[3]);
            *reinterpret_cast<float4*>(dst + 64 + cx * 4) =
                make_float4(o[4], o[5], o[6], o[7]);
        }
    }
}

// ============================ fused edge softmax-aggregate ==================
// 32-lane lane-owns-head layout (reverted from R15's 16-lane regression):
// 4 nodes/warp, lane = sub*8+head, zero shuffles per edge, alternating buffers.
template <int C, bool FINAL>
__global__ __launch_bounds__(256) void k_edge(const float* __restrict__ attl,
                                              const float* __restrict__ attr,
                                              const float* __restrict__ bias,
                                              float* __restrict__ outFinal) {
    constexpr int F = 8 * C;

    int warp = (blockIdx.x * blockDim.x + threadIdx.x) >> 5;
    int lane = threadIdx.x & 31;
    int sub  = lane >> 3;
    int head = lane & 7;
    int i = warp * 4 + sub;
    if (i >= Nn) return;

    const float* __restrict__ h = FINAL ? (const float*)g_h2 : (const float*)g_h1;

    float xi[C], wl[C], acc[C];
    float ar = 0.f;
    const float* hi = h + (size_t)i * F + head * C;
#pragma unroll
    for (int c4 = 0; c4 < C; c4 += 4) {
        float4 v = *reinterpret_cast<const float4*>(hi + c4);
        xi[c4 + 0] = v.x; xi[c4 + 1] = v.y; xi[c4 + 2] = v.z; xi[c4 + 3] = v.w;
    }
#pragma unroll
    for (int c = 0; c < C; c++) {
        wl[c] = attl[head * C + c];
        ar = fmaf(xi[c], attr[head * C + c], ar);
        acc[c] = 0.f;
    }

    int e0 = g_offsets[i];
    int e1 = g_offsets[i + 1];
    float d = 0.f;

    auto loadrow = [&](float* xj, int src) {
        const float* hp = h + (size_t)src * F + head * C;
#pragma unroll
        for (int c4 = 0; c4 < C; c4 += 4) {
            float4 v = *reinterpret_cast<const float4*>(hp + c4);
            xj[c4 + 0] = v.x; xj[c4 + 1] = v.y; xj[c4 + 2] = v.z; xj[c4 + 3] = v.w;
        }
    };
    auto process = [&](const float* xj) {
        float lg = 0.f, al = 0.f;
#pragma unroll
        for (int c = 0; c < C; c++) {
            lg = fmaf(xi[c], xj[c], lg);
            al = fmaf(wl[c], xj[c], al);
        }
        float sig = 1.f / (1.f + __expf(-lg));
        float a = (al + ar) * sig;
        a = (a > 0.f) ? a : NEG_SLOPE * a;
        float w = __expf(a);
        d += w;
#pragma unroll
        for (int c = 0; c < C; c++) acc[c] = fmaf(w, xj[c], acc[c]);
    };

    float xj0[C], xj1[C];
    loadrow(xj0, g_col[e0]);
    int e = e0;
    for (;;) {
        loadrow(xj1, g_col[e + 1]);    // pad-safe prefetch
        process(xj0);
        if (++e >= e1) break;
        loadrow(xj0, g_col[e + 1]);
        process(xj1);
        if (++e >= e1) break;
    }

    float inv = 1.f / (d + 1e-16f);

    if constexpr (!FINAL) {
        float* o = g_h1act + (size_t)i * F + head * C;
#pragma unroll
        for (int c4 = 0; c4 < C; c4 += 4) {
            float v[4];
#pragma unroll
            for (int j = 0; j < 4; j++) {
                float t = acc[c4 + j] * inv + bias[head * C + c4 + j];
                v[j] = (t > 0.f) ? t : expm1f(t);
            }
            *reinterpret_cast<float4*>(o + c4) = make_float4(v[0], v[1], v[2], v[3]);
        }
    } else {
        float v[C];
#pragma unroll
        for (int c = 0; c < C; c++) {
            float s = acc[c] * inv;
            s += __shfl_xor_sync(0xffffffffu, s, 1);
            s += __shfl_xor_sync(0xffffffffu, s, 2);
            s += __shfl_xor_sync(0xffffffffu, s, 4);
            v[c] = s * 0.125f + bias[c];
        }
        if (head == 0) {
            float mx = v[0];
#pragma unroll
            for (int c = 1; c < C; c++) mx = fmaxf(mx, v[c]);
            float se = 0.f;
#pragma unroll
            for (int c = 0; c < C; c++) se += __expf(v[c] - mx);
            float lse = mx + logf(se);
            float* o = outFinal + (size_t)i * 16;
#pragma unroll
            for (int c4 = 0; c4 < C; c4 += 4)
                *reinterpret_cast<float4*>(o + c4) =
                    make_float4(v[c4] - lse, v[c4 + 1] - lse, v[c4 + 2] - lse, v[c4 + 3] - lse);
        }
    }
}

// ============================ launch ========================================
extern "C" void kernel_launch(void* const* d_in, const int* in_sizes, int n_in,
                              void* d_out, int out_size) {
    (void)in_sizes; (void)n_in; (void)out_size;
    const float* x     = (const float*)d_in[0];
    const void*  ei    = d_in[1];
    const float* W1    = (const float*)d_in[2];
    const float* attl1 = (const float*)d_in[3];
    const float* attr1 = (const float*)d_in[4];
    const float* b1    = (const float*)d_in[5];
    const float* W2    = (const float*)d_in[6];
    const float* attl2 = (const float*)d_in[7];
    const float* attr2 = (const float*)d_in[8];
    const float* b2    = (const float*)d_in[9];
    float* out = (float*)d_out;

    // k_gemm1 stays at launch index 3 (the slot ncu captures).
    k_detect<<<1, 64>>>(ei);                              // 0
    k_init_count<<<(Nn + 255) / 256, 256>>>();            // 1
    k_count<<<(Ee + 255) / 256, 256>>>(ei);               // 2
    k_gemm1<<<(Nn + 127) / 128, 256>>>(x, W1);            // 3
    k_scan1<<<98, 256>>>();                               // 4
    k_scan2<<<1, 32>>>();                                 // 5
    k_scan3<<<(Nn + 255) / 256, 256>>>();                 // 6
    k_fill<<<(NE_TOT + 255) / 256, 256>>>(ei);            // 7

    // Layer 1 aggregate (4 nodes/warp)
    k_edge<8, false><<<(Nn + 31) / 32, 256>>>(attl1, attr1, b1, nullptr);

    // Layer 2
    k_gemm2<<<(Nn + 63) / 64, 256>>>(W2);
    k_edge<16, true><<<(Nn + 31) / 32, 256>>>(attl2, attr2, b2, out);
}

// round 17
// speedup vs baseline: 1.2246x; 1.2246x over previous
#include <cuda_runtime.h>
#include <math.h>
#include <stdint.h>

// Problem constants (fixed by the dataset)
#define Nn 100000
#define Ee 1600000
#define NE_TOT (Ee + Nn)          // edges + self loops
#define F1 64                     // heads*hid  (8*8)
#define F2 128                    // heads*out  (8*16)
#define IN_CH 512
#define NEG_SLOPE 0.2f

// ---------------- device scratch (static allocation: allowed) ----------------
__device__ int   g_is64;          // 1 if edge_index is int64, 0 if int32
__device__ int   g_count[Nn];
__device__ int   g_offsets[Nn + 1];
__device__ int   g_bsum[128];
__device__ int   g_cursor[Nn];
__device__ int   g_col[NE_TOT + 8];   // +8 pad (zero-init): prefetch-safe
__device__ __align__(16) float g_h1[(size_t)Nn * F1];     // gemm1 output
__device__ __align__(16) float g_h1act[(size_t)Nn * F1];  // layer1 aggregated + elu
__device__ __align__(16) float g_h2[(size_t)Nn * F2];     // gemm2 output

// ---------------- cp.async helpers ------------------------------------------
__device__ __forceinline__ uint32_t smem_u32(const void* p) {
    return (uint32_t)__cvta_generic_to_shared(p);
}
__device__ __forceinline__ void cp_async16(uint32_t dst, const void* src, int src_bytes) {
    asm volatile("cp.async.ca.shared.global [%0], [%1], 16, %2;"
                 :: "r"(dst), "l"(src), "r"(src_bytes));
}
__device__ __forceinline__ void cp_commit() {
    asm volatile("cp.async.commit_group;");
}
__device__ __forceinline__ void cp_wait_all() {
    asm volatile("cp.async.wait_group 0;");
}

// ---------------- tf32 helpers ----------------------------------------------
__device__ __forceinline__ uint32_t f2tf32(float f) {
    uint32_t u;
    asm("cvt.rna.tf32.f32 %0, %1;" : "=r"(u) : "f"(f));
    return u;
}
__device__ __forceinline__ void mma_tf32(float& c0, float& c1, float& c2, float& c3,
                                         uint32_t a0, uint32_t a1, uint32_t a2, uint32_t a3,
                                         uint32_t b0, uint32_t b1) {
    asm volatile(
        "mma.sync.aligned.m16n8k8.row.col.f32.tf32.tf32.f32 "
        "{%0,%1,%2,%3}, {%4,%5,%6,%7}, {%8,%9}, {%0,%1,%2,%3};"
        : "+f"(c0), "+f"(c1), "+f"(c2), "+f"(c3)
        : "r"(a0), "r"(a1), "r"(a2), "r"(a3), "r"(b0), "r"(b1));
}

// ============================ dtype detection ===============================
__global__ void k_detect(const void* ei) {
    __shared__ int s_bad;
    if (threadIdx.x == 0) s_bad = 0;
    __syncthreads();
    long long v = ((const long long*)ei)[threadIdx.x];   // 64 threads
    if (v < 0 || v >= Nn) atomicAdd(&s_bad, 1);
    __syncthreads();
    if (threadIdx.x == 0) g_is64 = (s_bad == 0) ? 1 : 0;
}

__device__ __forceinline__ int load_idx(const void* ei, size_t pos, int is64) {
    return is64 ? (int)((const long long*)ei)[pos] : ((const int*)ei)[pos];
}

// ============================ CSR build =====================================
__global__ void k_init_count() {
    int i = blockIdx.x * blockDim.x + threadIdx.x;
    if (i < Nn) g_count[i] = 1;   // self loop
}

__global__ void k_count(const void* __restrict__ ei) {
    int e = blockIdx.x * blockDim.x + threadIdx.x;
    if (e < Ee) {
        int is64 = g_is64;
        int dst = load_idx(ei, (size_t)Ee + e, is64);
        if ((unsigned)dst < (unsigned)Nn)
            atomicAdd(&g_count[dst], 1);
    }
}

__global__ void k_scan1() {
    __shared__ int warpsum[8];
    int t = threadIdx.x;
    int lane = t & 31;
    int wid = t >> 5;
    int base = blockIdx.x * 1024 + t * 4;

    int c0 = (base + 0 < Nn) ? g_count[base + 0] : 0;
    int c1 = (base + 1 < Nn) ? g_count[base + 1] : 0;
    int c2 = (base + 2 < Nn) ? g_count[base + 2] : 0;
    int c3 = (base + 3 < Nn) ? g_count[base + 3] : 0;
    int tot = c0 + c1 + c2 + c3;

    int v = tot;
#pragma unroll
    for (int off = 1; off < 32; off <<= 1) {
        int n = __shfl_up_sync(0xffffffffu, v, off);
        if (lane >= off) v += n;
    }
    if (lane == 31) warpsum[wid] = v;
    __syncthreads();
    if (t == 0) {
        int run = 0;
#pragma unroll
        for (int i = 0; i < 8; i++) { int x = warpsum[i]; warpsum[i] = run; run += x; }
    }
    __syncthreads();

    int exc = warpsum[wid] + (v - tot);
    if (base + 0 < Nn) g_offsets[base + 0] = exc;
    exc += c0;
    if (base + 1 < Nn) g_offsets[base + 1] = exc;
    exc += c1;
    if (base + 2 < Nn) g_offsets[base + 2] = exc;
    exc += c2;
    if (base + 3 < Nn) g_offsets[base + 3] = exc;

    if (t == 255) g_bsum[blockIdx.x] = warpsum[7] + v;
}

__global__ void k_scan2() {
    int lane = threadIdx.x;   // <<<1,32>>>
    int run = 0;
#pragma unroll
    for (int c = 0; c < 4; c++) {
        int idx = c * 32 + lane;
        int x = (idx < 98) ? g_bsum[idx] : 0;
        int v = x;
#pragma unroll
        for (int off = 1; off < 32; off <<= 1) {
            int n = __shfl_up_sync(0xffffffffu, v, off);
            if (lane >= off) v += n;
        }
        if (idx < 98) g_bsum[idx] = run + (v - x);
        run += __shfl_sync(0xffffffffu, v, 31);
    }
}

__global__ void k_scan3() {
    int g = blockIdx.x * blockDim.x + threadIdx.x;
    if (g < Nn) {
        int o = g_offsets[g] + g_bsum[g >> 10];
        g_offsets[g] = o;
        g_cursor[g] = o;
    }
    if (g == 0) g_offsets[Nn] = NE_TOT;
}

__global__ void k_fill(const void* __restrict__ ei) {
    int t = blockIdx.x * blockDim.x + threadIdx.x;
    if (t >= NE_TOT) return;
    if (t < Ee) {
        int is64 = g_is64;
        int src = load_idx(ei, (size_t)t, is64);
        int dst = load_idx(ei, (size_t)Ee + t, is64);
        if ((unsigned)src < (unsigned)Nn && (unsigned)dst < (unsigned)Nn) {
            int pos = atomicAdd(&g_cursor[dst], 1);
            if ((unsigned)pos < (unsigned)NE_TOT) g_col[pos] = src;
        }
    } else {
        int i = t - Ee;
        int pos = atomicAdd(&g_cursor[i], 1);
        if ((unsigned)pos < (unsigned)NE_TOT) g_col[pos] = i;   // self loop
    }
}

// ============================ GEMM 1: x[N,512] @ W1[512,64] =================
// tf32 tensor-core version. 256 threads (8 warps), block tile 128x64.
// Warp w computes rows w*16..w*16+15 x all 64 cols (8 m16n8 tiles), k8 steps.
// Smem pads chosen so all fragment loads are bank-conflict-free:
//   A pad 36: bank = 4*grp + qid (32 distinct)
//   B pad 72: bank = 8*qid + grp (32 distinct)
__global__ __launch_bounds__(256) void k_gemm1(const float* __restrict__ x,
                                               const float* __restrict__ W) {
    __shared__ float As[128][36];   // 18432 B
    __shared__ float Bs[32][72];    //  9216 B

    int tid  = threadIdx.x;
    int wid  = tid >> 5;     // 0..7
    int lane = tid & 31;
    int grp  = lane >> 2;    // t/4: 0..7
    int qid  = lane & 3;     // t%4
    int row0 = blockIdx.x * 128;
    int arow = wid * 16 + grp;      // fragment row (and +8)

    float acc[8][4];
#pragma unroll
    for (int nt = 0; nt < 8; nt++)
#pragma unroll
        for (int c = 0; c < 4; c++) acc[nt][c] = 0.f;

    for (int tile = 0; tile < 16; tile++) {
        int k0 = tile * 32;
        // A: 128 rows x 32 k = 1024 float4 / 256 thr
#pragma unroll
        for (int it = 0; it < 4; it++) {
            int s = it * 256 + tid;
            int r = s >> 3;              // 0..127
            int kq = s & 7;
            int grow = row0 + r;
            const float* src = x + (size_t)(grow < Nn ? grow : 0) * IN_CH + k0 + kq * 4;
            cp_async16(smem_u32(&As[r][kq * 4]), src, (grow < Nn) ? 16 : 0);
        }
        // B: 32 k x 64 n = 512 float4 / 256 thr
#pragma unroll
        for (int it = 0; it < 2; it++) {
            int s = it * 256 + tid;
            int kk = s >> 4;             // 0..31
            int cq = s & 15;
            cp_async16(smem_u32(&Bs[kk][cq * 4]), W + (size_t)(k0 + kk) * F1 + cq * 4, 16);
        }
        cp_commit();
        cp_wait_all();
        __syncthreads();

#pragma unroll
        for (int k8 = 0; k8 < 4; k8++) {
            int kb = k8 * 8;
            uint32_t a0 = f2tf32(As[arow][kb + qid]);
            uint32_t a1 = f2tf32(As[arow + 8][kb + qid]);
            uint32_t a2 = f2tf32(As[arow][kb + 4 + qid]);
            uint32_t a3 = f2tf32(As[arow + 8][kb + 4 + qid]);
#pragma unroll
            for (int nt = 0; nt < 8; nt++) {
                uint32_t b0 = f2tf32(Bs[kb + qid][nt * 8 + grp]);
                uint32_t b1 = f2tf32(Bs[kb + 4 + qid][nt * 8 + grp]);
                mma_tf32(acc[nt][0], acc[nt][1], acc[nt][2], acc[nt][3],
                         a0, a1, a2, a3, b0, b1);
            }
        }
        __syncthreads();
    }

    // store: c0,c1 -> row arow, cols nt*8 + 2*qid(+1); c2,c3 -> row arow+8
    int r0g = row0 + arow;
    int r1g = row0 + arow + 8;
#pragma unroll
    for (int nt = 0; nt < 8; nt++) {
        if (r0g < Nn)
            *reinterpret_cast<float2*>(&g_h1[(size_t)r0g * F1 + nt * 8 + 2 * qid]) =
                make_float2(acc[nt][0], acc[nt][1]);
        if (r1g < Nn)
            *reinterpret_cast<float2*>(&g_h1[(size_t)r1g * F1 + nt * 8 + 2 * qid]) =
                make_float2(acc[nt][2], acc[nt][3]);
    }
}

// ============================ GEMM 2: h1act[N,64] @ W2[64,128] ==============
// (R13 version — scalar fmaf, conflict-free col remap)
__global__ void k_gemm2(const float* __restrict__ W) {
    __shared__ float As[64][65];
    __shared__ float Bs[32][132];

    int tid = threadIdx.x;
    int row0 = blockIdx.x * 64;
    int ry = tid >> 4;
    int cx = tid & 15;

#pragma unroll
    for (int it = 0; it < 4; it++) {
        int s = it * 256 + tid;
        int r = s >> 4;
        int kq = s & 15;
        int grow = row0 + r;
        float4 v = make_float4(0.f, 0.f, 0.f, 0.f);
        if (grow < Nn)
            v = *reinterpret_cast<const float4*>(&g_h1act[(size_t)grow * F1 + kq * 4]);
        As[kq * 4 + 0][r] = v.x;
        As[kq * 4 + 1][r] = v.y;
        As[kq * 4 + 2][r] = v.z;
        As[kq * 4 + 3][r] = v.w;
    }

    float acc[4][8];
#pragma unroll
    for (int r = 0; r < 4; r++)
#pragma unroll
        for (int c = 0; c < 8; c++) acc[r][c] = 0.f;

    for (int kc = 0; kc < 64; kc += 32) {
#pragma unroll
        for (int it = 0; it < 4; it++) {
            int s = it * 256 + tid;
            int kk = s >> 5;
            int cq = s & 31;
            float4 v = *reinterpret_cast<const float4*>(W + (size_t)(kc + kk) * F2 + cq * 4);
            *reinterpret_cast<float4*>(&Bs[kk][cq * 4]) = v;
        }
        __syncthreads();

#pragma unroll
        for (int k = 0; k < 32; k++) {
            float a[4];
#pragma unroll
            for (int j = 0; j < 4; j++) a[j] = As[kc + k][ry * 4 + j];
            float4 b0 = *reinterpret_cast<const float4*>(&Bs[k][cx * 4]);
            float4 b1 = *reinterpret_cast<const float4*>(&Bs[k][64 + cx * 4]);
            float b[8] = {b0.x, b0.y, b0.z, b0.w, b1.x, b1.y, b1.z, b1.w};
#pragma unroll
            for (int r = 0; r < 4; r++)
#pragma unroll
                for (int c = 0; c < 8; c++) acc[r][c] = fmaf(a[r], b[c], acc[r][c]);
        }
        __syncthreads();
    }

#pragma unroll
    for (int r = 0; r < 4; r++) {
        int grow = row0 + ry * 4 + r;
        if (grow < Nn) {
            float* dst = &g_h2[(size_t)grow * F2];
            *reinterpret_cast<float4*>(dst + cx * 4) =
                make_float4(acc[r][0], acc[r][1], acc[r][2], acc[r][3]);
            *reinterpret_cast<float4*>(dst + 64 + cx * 4) =
                make_float4(acc[r][4], acc[r][5], acc[r][6], acc[r][7]);
        }
    }
}

// ============================ fused edge softmax-aggregate ==================
// (R13 version — lane-owns-head, 1-ahead prefetch with register rotate,
//  direct exp; scores bounded so no running max needed)
template <int C, bool FINAL>
__global__ __launch_bounds__(256) void k_edge(const float* __restrict__ attl,
                                              const float* __restrict__ attr,
                                              const float* __restrict__ bias,
                                              float* __restrict__ outFinal) {
    constexpr int F = 8 * C;

    int warp = (blockIdx.x * blockDim.x + threadIdx.x) >> 5;
    int lane = threadIdx.x & 31;
    int sub  = lane >> 3;
    int head = lane & 7;
    int i = warp * 4 + sub;
    if (i >= Nn) return;

    const float* __restrict__ h = FINAL ? (const float*)g_h2 : (const float*)g_h1;

    float xi[C], wl[C], acc[C];
    float ar = 0.f;
    const float* hi = h + (size_t)i * F + head * C;
#pragma unroll
    for (int c4 = 0; c4 < C; c4 += 4) {
        float4 v = *reinterpret_cast<const float4*>(hi + c4);
        xi[c4 + 0] = v.x; xi[c4 + 1] = v.y; xi[c4 + 2] = v.z; xi[c4 + 3] = v.w;
    }
#pragma unroll
    for (int c = 0; c < C; c++) {
        wl[c] = attl[head * C + c];
        ar = fmaf(xi[c], attr[head * C + c], ar);
        acc[c] = 0.f;
    }

    int e0 = g_offsets[i];
    int e1 = g_offsets[i + 1];

    float d = 0.f;

    float xjA[C];
    {
        int src0 = g_col[e0];
        const float* hj = h + (size_t)src0 * F + head * C;
#pragma unroll
        for (int c4 = 0; c4 < C; c4 += 4) {
            float4 v = *reinterpret_cast<const float4*>(hj + c4);
            xjA[c4 + 0] = v.x; xjA[c4 + 1] = v.y; xjA[c4 + 2] = v.z; xjA[c4 + 3] = v.w;
        }
    }

    for (int e = e0; e < e1; e++) {
        int nsrc = g_col[e + 1];          // g_col padded: safe at e1
        float xjB[C];
        const float* hn = h + (size_t)nsrc * F + head * C;
#pragma unroll
        for (int c4 = 0; c4 < C; c4 += 4) {
            float4 v = *reinterpret_cast<const float4*>(hn + c4);
            xjB[c4 + 0] = v.x; xjB[c4 + 1] = v.y; xjB[c4 + 2] = v.z; xjB[c4 + 3] = v.w;
        }

        float lg = 0.f, al = 0.f;
#pragma unroll
        for (int c = 0; c < C; c++) {
            lg = fmaf(xi[c], xjA[c], lg);
            al = fmaf(wl[c], xjA[c], al);
        }
        float sig = 1.f / (1.f + __expf(-lg));
        float a = (al + ar) * sig;
        a = (a > 0.f) ? a : NEG_SLOPE * a;

        float w = __expf(a);
        d += w;
#pragma unroll
        for (int c = 0; c < C; c++) acc[c] = fmaf(w, xjA[c], acc[c]);

#pragma unroll
        for (int c = 0; c < C; c++) xjA[c] = xjB[c];
    }

    float inv = 1.f / (d + 1e-16f);

    if constexpr (!FINAL) {
        float* o = g_h1act + (size_t)i * F + head * C;
#pragma unroll
        for (int c4 = 0; c4 < C; c4 += 4) {
            float v[4];
#pragma unroll
            for (int j = 0; j < 4; j++) {
                float t = acc[c4 + j] * inv + bias[head * C + c4 + j];
                v[j] = (t > 0.f) ? t : expm1f(t);
            }
            *reinterpret_cast<float4*>(o + c4) = make_float4(v[0], v[1], v[2], v[3]);
        }
    } else {
        float v[C];
#pragma unroll
        for (int c = 0; c < C; c++) {
            float s = acc[c] * inv;
            s += __shfl_xor_sync(0xffffffffu, s, 1);
            s += __shfl_xor_sync(0xffffffffu, s, 2);
            s += __shfl_xor_sync(0xffffffffu, s, 4);
            v[c] = s * 0.125f + bias[c];
        }
        if (head == 0) {
            float mx = v[0];
#pragma unroll
            for (int c = 1; c < C; c++) mx = fmaxf(mx, v[c]);
            float se = 0.f;
#pragma unroll
            for (int c = 0; c < C; c++) se += __expf(v[c] - mx);
            float lse = mx + logf(se);
            float* o = outFinal + (size_t)i * 16;
#pragma unroll
            for (int c4 = 0; c4 < C; c4 += 4)
                *reinterpret_cast<float4*>(o + c4) =
                    make_float4(v[c4] - lse, v[c4 + 1] - lse, v[c4 + 2] - lse, v[c4 + 3] - lse);
        }
    }
}

// ============================ launch ========================================
extern "C" void kernel_launch(void* const* d_in, const int* in_sizes, int n_in,
                              void* d_out, int out_size) {
    (void)in_sizes; (void)n_in; (void)out_size;
    const float* x     = (const float*)d_in[0];
    const void*  ei    = d_in[1];
    const float* W1    = (const float*)d_in[2];
    const float* attl1 = (const float*)d_in[3];
    const float* attr1 = (const float*)d_in[4];
    const float* b1    = (const float*)d_in[5];
    const float* W2    = (const float*)d_in[6];
    const float* attl2 = (const float*)d_in[7];
    const float* attr2 = (const float*)d_in[8];
    const float* b2    = (const float*)d_in[9];
    float* out = (float*)d_out;

    // k_gemm1 stays at launch index 3 (the slot ncu captures).
    k_detect<<<1, 64>>>(ei);                              // 0
    k_init_count<<<(Nn + 255) / 256, 256>>>();            // 1
    k_count<<<(Ee + 255) / 256, 256>>>(ei);               // 2
    k_gemm1<<<(Nn + 127) / 128, 256>>>(x, W1);            // 3
    k_scan1<<<98, 256>>>();                               // 4
    k_scan2<<<1, 32>>>();                                 // 5
    k_scan3<<<(Nn + 255) / 256, 256>>>();                 // 6
    k_fill<<<(NE_TOT + 255) / 256, 256>>>(ei);            // 7

    // Layer 1 aggregate (4 nodes/warp)
    k_edge<8, false><<<(Nn + 31) / 32, 256>>>(attl1, attr1, b1, nullptr);

    // Layer 2
    k_gemm2<<<(Nn + 63) / 64, 256>>>(W2);
    k_edge<16, true><<<(Nn + 31) / 32, 256>>>(attl2, attr2, b2, out);
}